// round 12
// baseline (speedup 1.0000x reference)
#include <cuda_runtime.h>
#include <cuda_bf16.h>
#include <cstdint>

#define HID    256
#define BATCH  64
#define TT     256
#define INDIM  64
#define OUTDIM 32

#define OUT_ELEMS   (BATCH*TT*OUTDIM)          // 524288
#define XF_OFF      OUT_ELEMS
#define TRAJ_OFF    (OUT_ELEMS + BATCH*HID)    // 540672

#define NCTA 128
#define NTHR 256

// ---------------- device globals (static scratch; no runtime allocation) ----------------
__device__ __nv_bfloat16 g_Wb[(size_t)HID * HID * HID];      // 33.5 MB bf16 W tensor [j][i][k]
__device__ float         g_Ieff[(size_t)TT * BATCH * HID];   // 16.8 MB
__device__ float         g_x[BATCH * HID];                   // state x [b][j]
__device__ __nv_bfloat16 g_rb[2][BATCH * HID];               // double-buffered r = tanh(x)
__device__ unsigned      g_barcnt = 0;
__device__ unsigned      g_bargen = 0;

// ---------------- mma helper (bf16 -> fp32, m16n8k16) ----------------
__device__ __forceinline__ void mma16816(float c[4], const unsigned a[4], const unsigned b[2]) {
    asm volatile(
        "mma.sync.aligned.m16n8k16.row.col.f32.bf16.bf16.f32 "
        "{%0,%1,%2,%3}, {%4,%5,%6,%7}, {%8,%9}, {%0,%1,%2,%3};\n"
        : "+f"(c[0]), "+f"(c[1]), "+f"(c[2]), "+f"(c[3])
        : "r"(a[0]), "r"(a[1]), "r"(a[2]), "r"(a[3]), "r"(b[0]), "r"(b[1]));
}

// ---------------- software grid barrier (all CTAs resident) ----------------
__device__ __forceinline__ void gridbar() {
    __syncthreads();
    __threadfence();
    if (threadIdx.x == 0) {
        unsigned gen  = atomicAdd(&g_bargen, 0u);
        unsigned prev = atomicAdd(&g_barcnt, 1u);
        if (prev == gridDim.x - 1u) {
            atomicExch(&g_barcnt, 0u);
            __threadfence();
            atomicAdd(&g_bargen, 1u);
        } else {
            while (atomicAdd(&g_bargen, 0u) == gen) { __nanosleep(64); }
        }
    }
    __threadfence();
    __syncthreads();
}

// ---------------- prologue: fp32 W -> bf16 ----------------
__global__ void k_conv(const float* __restrict__ W) {
    size_t i = (size_t)blockIdx.x * blockDim.x + threadIdx.x;
    size_t n2 = (size_t)HID * HID * HID / 2;
    if (i < n2) {
        float2 v = ((const float2*)W)[i];
        ((__nv_bfloat162*)g_Wb)[i] = __floats2bfloat162_rn(v.x, v.y);
    }
}

// ---------------- prologue: init state ----------------
__global__ void k_init(const float* __restrict__ x0) {
    int i = blockIdx.x * blockDim.x + threadIdx.x;
    if (i < BATCH * HID) {
        float v = x0[i];
        g_x[i] = v;
        g_rb[0][i] = __float2bfloat16(tanhf(v));
    }
}

// ---------------- prologue: Ieff[t][b][h] = 0.05*noise + 0.2*(u[b,t,:]@win[h,:] + winb[h]) ----------------
__global__ void k_ieff(const float* __restrict__ u, const float* __restrict__ noise,
                       const float* __restrict__ winw, const float* __restrict__ winb) {
    __shared__ float us[BATCH][INDIM];  // 16 KB
    int t = blockIdx.x;
    int h = threadIdx.x;
    for (int idx = h; idx < BATCH * INDIM; idx += blockDim.x) {
        int b = idx / INDIM, in = idx % INDIM;
        us[b][in] = u[((size_t)b * TT + t) * INDIM + in];
    }
    __syncthreads();
    float wreg[INDIM];
    #pragma unroll
    for (int in = 0; in < INDIM; ++in) wreg[in] = winw[h * INDIM + in];
    float bias = winb[h];
    for (int b = 0; b < BATCH; ++b) {
        float acc = bias;
        #pragma unroll
        for (int in = 0; in < INDIM; ++in) acc += us[b][in] * wreg[in];
        size_t off = ((size_t)t * BATCH + b) * HID + h;
        g_Ieff[off] = 0.05f * noise[off] + 0.2f * acc;
    }
}

// ---------------- main persistent kernel ----------------
__global__ void __launch_bounds__(NTHR, 1)
k_main(const float* __restrict__ whh_g, float* __restrict__ dout) {
    __shared__ __nv_bfloat16 rs[64 * 264];   // padded rows (264 bf16 = 528B stride) -> bank-conflict-free
    __shared__ float reds[8][64];
    __shared__ float w2s[2][64];
    __shared__ float whh[2][HID];

    const int tid  = threadIdx.x;
    const int warp = tid >> 5;
    const int lane = tid & 31;
    const int lq   = lane >> 2;   // 0..7
    const int lr   = lane & 3;    // 0..3
    const int j0   = blockIdx.x * 2;
    const int nbase = warp * 32;

    const uint32_t* rsw = (const uint32_t*)rs;
    float* traj = dout + TRAJ_OFF;

    // preload w_hh_rnn rows j0, j0+1
    whh[0][tid] = whh_g[(size_t)j0 * HID + tid];
    whh[1][tid] = whh_g[(size_t)(j0 + 1) * HID + tid];

    int cur = 0;
    for (int t = 0; t < TT; ++t) {
        // stage r[cur] into padded smem
        const uint4* src = (const uint4*)g_rb[cur];
        #pragma unroll
        for (int idx = tid; idx < 64 * 32; idx += NTHR) {
            int row = idx >> 5, c = idx & 31;
            ((uint4*)rs)[row * 33 + c] = src[idx];   // 33 uint4 = 264 bf16 stride
        }
        __syncthreads();

        // ---- per owned j: GEMM C[b,i] = sum_k r[b,k] * W[j,i,k], fused W2 epilogue ----
        for (int jj = 0; jj < 2; ++jj) {
            const int j = j0 + jj;
            const uint32_t* Wjw = (const uint32_t*)(g_Wb + (size_t)j * (HID * HID));

            float acc[4][4][4];
            #pragma unroll
            for (int m = 0; m < 4; ++m)
                #pragma unroll
                for (int n = 0; n < 4; ++n)
                    #pragma unroll
                    for (int f = 0; f < 4; ++f) acc[m][n][f] = 0.f;

            #pragma unroll 4
            for (int kt = 0; kt < 16; ++kt) {
                const int k0 = kt * 16 + lr * 2;
                unsigned a[4][4];
                #pragma unroll
                for (int m = 0; m < 4; ++m) {
                    int r0 = m * 16 + lq;
                    a[m][0] = rsw[r0 * 132 + (k0 >> 1)];
                    a[m][1] = rsw[(r0 + 8) * 132 + (k0 >> 1)];
                    a[m][2] = rsw[r0 * 132 + ((k0 + 8) >> 1)];
                    a[m][3] = rsw[(r0 + 8) * 132 + ((k0 + 8) >> 1)];
                }
                unsigned bf[4][2];
                #pragma unroll
                for (int n = 0; n < 4; ++n) {
                    int nc = nbase + n * 8 + lq;            // i index
                    bf[n][0] = __ldg(&Wjw[(nc * HID + k0) >> 1]);
                    bf[n][1] = __ldg(&Wjw[(nc * HID + k0 + 8) >> 1]);
                }
                #pragma unroll
                for (int m = 0; m < 4; ++m)
                    #pragma unroll
                    for (int n = 0; n < 4; ++n)
                        mma16816(acc[m][n], a[m], bf[n]);
            }

            // epilogue: p[b] = sum_i r[b,i]*C[b,i] (per-thread partials)
            float p[8];
            #pragma unroll
            for (int m = 0; m < 8; ++m) p[m] = 0.f;
            #pragma unroll
            for (int m = 0; m < 4; ++m) {
                int b0 = m * 16 + lq, b1 = b0 + 8;
                #pragma unroll
                for (int n = 0; n < 4; ++n) {
                    int i0 = nbase + n * 8 + lr * 2;
                    float r00 = __bfloat162float(rs[b0 * 264 + i0]);
                    float r01 = __bfloat162float(rs[b0 * 264 + i0 + 1]);
                    float r10 = __bfloat162float(rs[b1 * 264 + i0]);
                    float r11 = __bfloat162float(rs[b1 * 264 + i0 + 1]);
                    p[2 * m]     += acc[m][n][0] * r00 + acc[m][n][1] * r01;
                    p[2 * m + 1] += acc[m][n][2] * r10 + acc[m][n][3] * r11;
                }
            }
            #pragma unroll
            for (int m = 0; m < 8; ++m) {
                p[m] += __shfl_xor_sync(0xFFFFFFFFu, p[m], 1);
                p[m] += __shfl_xor_sync(0xFFFFFFFFu, p[m], 2);
            }
            if (lr == 0) {
                #pragma unroll
                for (int m = 0; m < 4; ++m) {
                    reds[warp][m * 16 + lq]     = p[2 * m];
                    reds[warp][m * 16 + lq + 8] = p[2 * m + 1];
                }
            }
            __syncthreads();
            if (tid < 64) {
                float s = 0.f;
                #pragma unroll
                for (int w = 0; w < 8; ++w) s += reds[w][tid];
                w2s[jj][tid] = s;
            }
            __syncthreads();
        }

        // ---- W1 + state update for owned (jj,b) pairs ----
        if (tid < 128) {
            int jj = tid >> 6, b = tid & 63, j = j0 + jj;
            float w1 = 0.f;
            const uint32_t* rrow = rsw + b * 132;
            #pragma unroll 8
            for (int i2 = 0; i2 < 128; ++i2) {
                uint32_t rv = rrow[i2];
                __nv_bfloat162 r2 = *(__nv_bfloat162*)&rv;
                w1 += __bfloat162float(r2.x) * whh[jj][2 * i2]
                    + __bfloat162float(r2.y) * whh[jj][2 * i2 + 1];
            }
            float xo = g_x[b * HID + j];
            float xn = 0.8f * xo
                     + g_Ieff[((size_t)t * BATCH + b) * HID + j]
                     + 0.2f * (w1 + w2s[jj][b]);
            g_x[b * HID + j] = xn;
            traj[((size_t)b * TT + t) * HID + j] = xn;
            g_rb[cur ^ 1][b * HID + j] = __float2bfloat16(tanhf(xn));
        }

        gridbar();
        cur ^= 1;
    }
}

// ---------------- epilogue: output head ----------------
__global__ void k_head(const float* __restrict__ wo, const float* __restrict__ wob,
                       float* __restrict__ dout) {
    __shared__ float sh[HID];
    __shared__ float red[256];
    int row = blockIdx.x;  // b*TT + t
    const float* tr = dout + TRAJ_OFF + (size_t)row * HID;
    int tid = threadIdx.x;
    sh[tid] = tanhf(tr[tid]);
    __syncthreads();
    int o = tid & 31, sl = tid >> 5;
    float p = 0.f;
    const float* w = wo + o * HID + sl * 32;
    const float* s = sh + sl * 32;
    #pragma unroll
    for (int i = 0; i < 32; ++i) p += s[i] * __ldg(&w[i]);
    red[tid] = p;
    __syncthreads();
    if (tid < 32) {
        float s2 = red[tid];
        #pragma unroll
        for (int k = 1; k < 8; ++k) s2 += red[tid + 32 * k];
        dout[(size_t)row * OUTDIM + tid] = s2 + wob[tid];
    }
}

// ---------------- epilogue: x_final copy ----------------
__global__ void k_xf(float* __restrict__ dout) {
    int i = blockIdx.x * blockDim.x + threadIdx.x;
    if (i < BATCH * HID) dout[XF_OFF + i] = g_x[i];
}

extern "C" void kernel_launch(void* const* d_in, const int* in_sizes, int n_in,
                              void* d_out, int out_size) {
    const float* u      = (const float*)d_in[0];
    const float* x0     = (const float*)d_in[1];
    const float* noise  = (const float*)d_in[2];
    const float* whh    = (const float*)d_in[3];
    const float* wtb    = (const float*)d_in[4];
    const float* winw   = (const float*)d_in[5];
    const float* winb   = (const float*)d_in[6];
    const float* woutw  = (const float*)d_in[7];
    const float* woutb  = (const float*)d_in[8];
    float* dout = (float*)d_out;

    k_conv<<<32768, 256>>>(wtb);
    k_init<<<64, 256>>>(x0);
    k_ieff<<<TT, HID>>>(u, noise, winw, winb);
    k_main<<<NCTA, NTHR>>>(whh, dout);
    k_head<<<BATCH * TT, HID>>>(woutw, woutb, dout);
    k_xf<<<64, 256>>>(dout);
}